// round 2
// baseline (speedup 1.0000x reference)
#include <cuda_runtime.h>

// ---------------------------------------------------------------------------
// AFNO: bias linear + 2D ortho rFFT + block-diag complex MLP + irFFT
// Shapes: x (8,64,64,768); spectrum (8,64,33,768) complex (split r/i)
// ---------------------------------------------------------------------------

#define BB   8
#define HH   64
#define WW   64
#define CC   768
#define KWC  33           // W//2+1
#define NB   4
#define BS   192

#define SPEC_N (BB*HH*KWC*CC)   // 12,976,128

// scratch (allocation-free rule: __device__ globals)
__device__ float g_wr[SPEC_N];
__device__ float g_wi[SPEC_N];
__device__ float g_sr[SPEC_N];
__device__ float g_si[SPEC_N];

// twiddle matrices, transposed layout T[k*64 + m], zero-padded to 64x64
// stage 0: fwd rFFT along W (M=33,K=64)
// stage 1: fwd FFT along H, ortho /64 (M=K=64)
// stage 2: inv FFT along H (M=K=64)
// stage 3: inv rFFT along W, /64 + hermitian alpha (M=64,K=33)
__device__ float g_twA[4][4096];
__device__ float g_twB[4][4096];

__global__ void fill_tw_kernel() {
    const float PI_32 = 3.14159265358979323846f / 32.0f;
    for (int idx = threadIdx.x; idx < 4096; idx += blockDim.x) {
        int k = idx >> 6;
        int m = idx & 63;
        int t = (k * m) & 63;
        float ang = (float)t * PI_32;
        float s, c;
        sincosf(ang, &s, &c);
        // stage 0: k=w, m=kw
        g_twA[0][idx] = (m < KWC) ? c : 0.f;
        g_twB[0][idx] = (m < KWC) ? s : 0.f;
        // stage 1: k=h, m=kh  (ortho forward scale)
        g_twA[1][idx] = c * (1.f / 64.f);
        g_twB[1][idx] = s * (1.f / 64.f);
        // stage 2: k=kh, m=h
        g_twA[2][idx] = c;
        g_twB[2][idx] = -s;
        // stage 3: k=kw, m=w  (hermitian weights + ortho inverse scale)
        float al = (k == 0 || k == 32) ? 1.f : 2.f;
        g_twA[3][idx] = (k < KWC) ? al * c * (1.f / 64.f) : 0.f;
        g_twB[3][idx] = (k < KWC) ? -al * s * (1.f / 64.f) : 0.f;
    }
}

// ---------------------------------------------------------------------------
// Generic batched DFT-GEMM: outr = A@inr + B@ini ; outi = A@ini - B@inr
// CTA: one batch x 64-channel tile. 256 threads: n = tid&63, m-group = tid>>6
// ---------------------------------------------------------------------------
template <int STAGE>
__global__ __launch_bounds__(256) void dft_kernel(const float* __restrict__ xin,
                                                  float* __restrict__ xout) {
    constexpr bool INI  = (STAGE != 0);
    constexpr bool OUTI = (STAGE != 3);
    constexpr int  M    = (STAGE == 0) ? KWC : 64;
    constexpr int  K    = (STAGE == 3) ? KWC : 64;

    __shared__ float sA[4096];
    __shared__ float sB[4096];
    int tid = threadIdx.x;
    for (int i = tid; i < 4096; i += 256) {
        sA[i] = g_twA[STAGE][i];
        sB[i] = g_twB[STAGE][i];
    }
    __syncthreads();

    int bi = blockIdx.x;
    int n  = (tid & 63) + (blockIdx.y << 6);
    int mg = tid >> 6;

    long ibase, obase;
    int  iks, oms;
    if (STAGE == 0) {
        ibase = (long)bi * (WW * CC); iks = CC;
        obase = (long)bi * (KWC * CC); oms = CC;
    } else if (STAGE == 1 || STAGE == 2) {
        int b = bi / KWC, kw = bi % KWC;
        long base = (long)b * (HH * KWC * CC) + (long)kw * CC;
        ibase = base; obase = base;
        iks = KWC * CC; oms = KWC * CC;
    } else {
        ibase = (long)bi * (KWC * CC); iks = CC;
        obase = (long)bi * (WW * CC);  oms = CC;
    }

    const float* pir;
    const float* pii;
    float* por;
    float* poi;
    if (STAGE == 0) { pir = xin + ibase;  pii = xin + ibase;  por = g_wr + obase; poi = g_wi + obase; }
    else if (STAGE == 1) { pir = g_wr + ibase; pii = g_wi + ibase; por = g_sr + obase; poi = g_si + obase; }
    else if (STAGE == 2) { pir = g_sr + ibase; pii = g_si + ibase; por = g_wr + obase; poi = g_wi + obase; }
    else { pir = g_wr + ibase; pii = g_wi + ibase; por = xout + obase; poi = xout + obase; }

    float accr[16], acci[16];
#pragma unroll
    for (int i = 0; i < 16; i++) { accr[i] = 0.f; acci[i] = 0.f; }

    for (int kk = 0; kk < K; kk++) {
        float xr = pir[(long)kk * iks + n];
        float xi = 0.f;
        if (INI) xi = pii[(long)kk * iks + n];
        const float4* a4 = reinterpret_cast<const float4*>(sA + kk * 64 + mg * 16);
        const float4* b4 = reinterpret_cast<const float4*>(sB + kk * 64 + mg * 16);
#pragma unroll
        for (int q = 0; q < 4; q++) {
            float4 a = a4[q];
            float4 b = b4[q];
            float av[4] = {a.x, a.y, a.z, a.w};
            float bv[4] = {b.x, b.y, b.z, b.w};
#pragma unroll
            for (int j = 0; j < 4; j++) {
                int mm = q * 4 + j;
                if (INI) {
                    accr[mm] += av[j] * xr + bv[j] * xi;
                    if (OUTI) acci[mm] += av[j] * xi - bv[j] * xr;
                } else {
                    accr[mm] += av[j] * xr;
                    if (OUTI) acci[mm] -= bv[j] * xr;
                }
            }
        }
    }

#pragma unroll
    for (int mm = 0; mm < 16; mm++) {
        int m = mg * 16 + mm;
        if (M == 64 || m < M) {
            long o = (long)m * oms + n;
            if (STAGE == 3) por[o] += accr[mm];
            else            por[o]  = accr[mm];
            if (OUTI) poi[o] = acci[mm];
        }
    }
}

// ---------------------------------------------------------------------------
// Fused spectral MLP: per CTA = 16 frequency positions x one 192-block.
// 192 threads; thread k owns output column k.
//   r1 = relu(Xr W1r - Xi W1i + b1r); i1 = relu(Xr W1i + Xi W1r + b1i)
//   r2 = r1 W2r - i1 W2i + b2r;       i2 = r2 W2i + i1 W2r + b2i   (NB: new r2)
// in-place on g_sr / g_si
// ---------------------------------------------------------------------------
__global__ __launch_bounds__(192) void spectral_kernel(const float* __restrict__ w1,
                                                       const float* __restrict__ b1,
                                                       const float* __restrict__ w2,
                                                       const float* __restrict__ b2) {
    __shared__ float At[BS][20];  // transposed [d][row], stride 20 (16B aligned)
    __shared__ float Bt[BS][20];
    __shared__ float Ct[BS][20];

    int k   = threadIdx.x;
    int blk = blockIdx.y;
    long p0 = (long)blockIdx.x * 16;
    int cb  = blk * BS;

#pragma unroll
    for (int r = 0; r < 16; r++) {
        At[k][r] = g_sr[(p0 + r) * CC + cb + k];
        Bt[k][r] = g_si[(p0 + r) * CC + cb + k];
    }
    __syncthreads();

    const float* w1r = w1 + (long)blk * BS * BS;
    const float* w1i = w1 + (long)(NB + blk) * BS * BS;
    const float* w2r = w2 + (long)blk * BS * BS;
    const float* w2i = w2 + (long)(NB + blk) * BS * BS;

    float accr[16], acci[16];
    {
        float c0 = b1[blk * BS + k];
        float c1 = b1[(NB + blk) * BS + k];
#pragma unroll
        for (int r = 0; r < 16; r++) { accr[r] = c0; acci[r] = c1; }
    }

    // layer 1
    for (int d = 0; d < BS; d++) {
        float wr = w1r[d * BS + k];
        float wi = w1i[d * BS + k];
#pragma unroll
        for (int q = 0; q < 4; q++) {
            float4 x4 = *reinterpret_cast<const float4*>(&At[d][q * 4]);
            float4 y4 = *reinterpret_cast<const float4*>(&Bt[d][q * 4]);
            float xv[4] = {x4.x, x4.y, x4.z, x4.w};
            float yv[4] = {y4.x, y4.y, y4.z, y4.w};
#pragma unroll
            for (int j = 0; j < 4; j++) {
                accr[q * 4 + j] += xv[j] * wr - yv[j] * wi;
                acci[q * 4 + j] += xv[j] * wi + yv[j] * wr;
            }
        }
    }
#pragma unroll
    for (int r = 0; r < 16; r++) {
        accr[r] = fmaxf(accr[r], 0.f);
        acci[r] = fmaxf(acci[r], 0.f);
    }
    __syncthreads();  // all layer-1 reads of At/Bt done
#pragma unroll
    for (int r = 0; r < 16; r++) {
        Ct[k][r] = accr[r];   // r1
        Bt[k][r] = acci[r];   // i1 (overwrite Xi)
    }
    __syncthreads();

    // layer 2: r2 fully, plus the i1*W2r part of i2
    {
        float d0 = b2[blk * BS + k];
        float d1 = b2[(NB + blk) * BS + k];
#pragma unroll
        for (int r = 0; r < 16; r++) { accr[r] = d0; acci[r] = d1; }
    }
    for (int d = 0; d < BS; d++) {
        float wr = w2r[d * BS + k];
        float wi = w2i[d * BS + k];
#pragma unroll
        for (int q = 0; q < 4; q++) {
            float4 r14 = *reinterpret_cast<const float4*>(&Ct[d][q * 4]);
            float4 i14 = *reinterpret_cast<const float4*>(&Bt[d][q * 4]);
            float rv[4] = {r14.x, r14.y, r14.z, r14.w};
            float iv[4] = {i14.x, i14.y, i14.z, i14.w};
#pragma unroll
            for (int j = 0; j < 4; j++) {
                accr[q * 4 + j] += rv[j] * wr - iv[j] * wi;
                acci[q * 4 + j] += iv[j] * wr;
            }
        }
    }
    // write Yr = r2; stage r2 into At for the i2 pass
#pragma unroll
    for (int r = 0; r < 16; r++) g_sr[(p0 + r) * CC + cb + k] = accr[r];
#pragma unroll
    for (int r = 0; r < 16; r++) At[k][r] = accr[r];
    __syncthreads();

    // i2 += r2 * W2i
    for (int d = 0; d < BS; d++) {
        float wi = w2i[d * BS + k];
#pragma unroll
        for (int q = 0; q < 4; q++) {
            float4 r24 = *reinterpret_cast<const float4*>(&At[d][q * 4]);
            float rv[4] = {r24.x, r24.y, r24.z, r24.w};
#pragma unroll
            for (int j = 0; j < 4; j++) acci[q * 4 + j] += rv[j] * wi;
        }
    }
#pragma unroll
    for (int r = 0; r < 16; r++) g_si[(p0 + r) * CC + cb + k] = acci[r];
}

// ---------------------------------------------------------------------------
// Bias GEMM: out[p][c] = sum_k x[p][k] * bias_w[c][k] + bias_b[c]
// 128x128 tile, BK=16, 256 threads, 8x8 per-thread micro-tile
// ---------------------------------------------------------------------------
__global__ __launch_bounds__(256) void bias_gemm_kernel(const float* __restrict__ X,
                                                        const float* __restrict__ Wm,
                                                        const float* __restrict__ bb,
                                                        float* __restrict__ out) {
    __shared__ float As[16][128];
    __shared__ float Bs[16][128];

    const int m0 = blockIdx.y * 128;
    const int n0 = blockIdx.x * 128;
    int tid = threadIdx.x;
    int tx = tid & 15;
    int ty = tid >> 4;

    int lr = tid >> 1;          // 0..127
    int lk = (tid & 1) * 8;     // 0 or 8

    const float* xg = X  + (long)(m0 + lr) * CC + lk;
    const float* wg = Wm + (long)(n0 + lr) * CC + lk;

    float acc[8][8];
#pragma unroll
    for (int i = 0; i < 8; i++)
#pragma unroll
        for (int j = 0; j < 8; j++) acc[i][j] = 0.f;

    for (int k0 = 0; k0 < CC; k0 += 16) {
        float4 a0 = *reinterpret_cast<const float4*>(xg + k0);
        float4 a1 = *reinterpret_cast<const float4*>(xg + k0 + 4);
        float4 b0 = *reinterpret_cast<const float4*>(wg + k0);
        float4 b1 = *reinterpret_cast<const float4*>(wg + k0 + 4);
        __syncthreads();
        As[lk + 0][lr] = a0.x; As[lk + 1][lr] = a0.y; As[lk + 2][lr] = a0.z; As[lk + 3][lr] = a0.w;
        As[lk + 4][lr] = a1.x; As[lk + 5][lr] = a1.y; As[lk + 6][lr] = a1.z; As[lk + 7][lr] = a1.w;
        Bs[lk + 0][lr] = b0.x; Bs[lk + 1][lr] = b0.y; Bs[lk + 2][lr] = b0.z; Bs[lk + 3][lr] = b0.w;
        Bs[lk + 4][lr] = b1.x; Bs[lk + 5][lr] = b1.y; Bs[lk + 6][lr] = b1.z; Bs[lk + 7][lr] = b1.w;
        __syncthreads();

#pragma unroll
        for (int kq = 0; kq < 16; kq++) {
            float4 ra0 = *reinterpret_cast<const float4*>(&As[kq][ty * 8]);
            float4 ra1 = *reinterpret_cast<const float4*>(&As[kq][ty * 8 + 4]);
            float4 rb0 = *reinterpret_cast<const float4*>(&Bs[kq][tx * 8]);
            float4 rb1 = *reinterpret_cast<const float4*>(&Bs[kq][tx * 8 + 4]);
            float av[8] = {ra0.x, ra0.y, ra0.z, ra0.w, ra1.x, ra1.y, ra1.z, ra1.w};
            float bv[8] = {rb0.x, rb0.y, rb0.z, rb0.w, rb1.x, rb1.y, rb1.z, rb1.w};
#pragma unroll
            for (int i = 0; i < 8; i++)
#pragma unroll
                for (int j = 0; j < 8; j++) acc[i][j] += av[i] * bv[j];
        }
    }

#pragma unroll
    for (int i = 0; i < 8; i++) {
        long row = m0 + ty * 8 + i;
#pragma unroll
        for (int j = 0; j < 8; j++) {
            int col = n0 + tx * 8 + j;
            out[row * CC + col] = acc[i][j] + bb[col];
        }
    }
}

// ---------------------------------------------------------------------------
extern "C" void kernel_launch(void* const* d_in, const int* in_sizes, int n_in,
                              void* d_out, int out_size) {
    const float* x  = (const float*)d_in[0];
    const float* w1 = (const float*)d_in[1];
    const float* b1 = (const float*)d_in[2];
    const float* w2 = (const float*)d_in[3];
    const float* b2 = (const float*)d_in[4];
    const float* bw = (const float*)d_in[5];
    const float* bbv= (const float*)d_in[6];
    float* out = (float*)d_out;

    fill_tw_kernel<<<1, 256>>>();

    // bias = x @ bias_w^T + bias_b  (writes every out element)
    bias_gemm_kernel<<<dim3(6, 256), 256>>>(x, bw, bbv, out);

    // forward rFFT along W:  x -> g_w
    dft_kernel<0><<<dim3(BB * HH, 12), 256>>>(x, out);
    // forward FFT along H (ortho /64): g_w -> g_s
    dft_kernel<1><<<dim3(BB * KWC, 12), 256>>>(x, out);
    // spectral block MLP (in place on g_s)
    spectral_kernel<<<dim3((BB * HH * KWC) / 16, NB), 192>>>(w1, b1, w2, b2);
    // inverse FFT along H: g_s -> g_w
    dft_kernel<2><<<dim3(BB * KWC, 12), 256>>>(x, out);
    // inverse rFFT along W (/64), accumulate into out
    dft_kernel<3><<<dim3(BB * HH, 12), 256>>>(x, out);
}

// round 4
// speedup vs baseline: 1.3514x; 1.3514x over previous
#include <cuda_runtime.h>

// ---------------------------------------------------------------------------
// AFNO: bias linear + 2D ortho rFFT + block-diag complex MLP + irFFT
// Tensor-core (tf32 mma.sync) implementation.
// ---------------------------------------------------------------------------

#define BB   8
#define HH   64
#define WW   64
#define CC   768
#define KWC  33
#define NB   4
#define BS   192

#define SPEC_N (BB*HH*KWC*CC)      // 12,976,128
#define PADROWS (8*CC)             // zero pad for stage-3 K overread

// scratch (__device__ globals are zero-initialized; pad region never written)
__device__ float g_wr[SPEC_N + PADROWS];
__device__ float g_wi[SPEC_N + PADROWS];
__device__ float g_sr[SPEC_N];
__device__ float g_si[SPEC_N];

// twiddles, layout [k*64 + m]
__device__ float g_twA[4][4096];
__device__ float g_twB[4][4096];

__global__ void fill_tw_kernel() {
    const float PI_32 = 3.14159265358979323846f / 32.0f;
    for (int idx = threadIdx.x; idx < 4096; idx += blockDim.x) {
        int k = idx >> 6;
        int m = idx & 63;
        int t = (k * m) & 63;
        float ang = (float)t * PI_32;
        float s, c;
        sincosf(ang, &s, &c);
        g_twA[0][idx] = (m < KWC) ? c : 0.f;                 // fwd W: k=w, m=kw
        g_twB[0][idx] = (m < KWC) ? s : 0.f;
        g_twA[1][idx] = c * (1.f / 64.f);                    // fwd H (ortho /64)
        g_twB[1][idx] = s * (1.f / 64.f);
        g_twA[2][idx] = c;                                   // inv H
        g_twB[2][idx] = -s;
        float al = (k == 0 || k == 32) ? 1.f : 2.f;          // inv W (+hermitian, /64)
        g_twA[3][idx] = (k < KWC) ? al * c * (1.f / 64.f) : 0.f;
        g_twB[3][idx] = (k < KWC) ? -al * s * (1.f / 64.f) : 0.f;
    }
}

// ---------------------------------------------------------------------------
// tf32 mma helpers
// ---------------------------------------------------------------------------
__device__ __forceinline__ unsigned f2tf(float f) {
    unsigned r;
    asm("cvt.rna.tf32.f32 %0, %1;" : "=r"(r) : "f"(f));
    return r;
}

__device__ __forceinline__ void mma8(float* d, const unsigned* a, const unsigned* b) {
    asm volatile(
        "mma.sync.aligned.m16n8k8.row.col.f32.tf32.tf32.f32 "
        "{%0,%1,%2,%3}, {%4,%5,%6,%7}, {%8,%9}, {%0,%1,%2,%3};"
        : "+f"(d[0]), "+f"(d[1]), "+f"(d[2]), "+f"(d[3])
        : "r"(a[0]), "r"(a[1]), "r"(a[2]), "r"(a[3]), "r"(b[0]), "r"(b[1]));
}

// ---------------------------------------------------------------------------
// Bias GEMM (3xTF32, near-fp32 accuracy):
//   out[m][n] = sum_k X[m][k] * W[n][k] + bias[n],  M=32768, N=K=768
// CTA tile 128x128, 8 warps (2m x 4n), warp tile 64x32.
// ---------------------------------------------------------------------------
__global__ __launch_bounds__(256) void bias_gemm_tc(const float* __restrict__ X,
                                                    const float* __restrict__ Wm,
                                                    const float* __restrict__ bb,
                                                    float* __restrict__ out) {
    __shared__ float As[128][20];
    __shared__ float Bs[128][20];

    int tid = threadIdx.x;
    int wid = tid >> 5, lane = tid & 31;
    int g = lane >> 2, tg = lane & 3;
    int wm = wid >> 2, wn = wid & 3;
    int m0 = blockIdx.y * 128, n0 = blockIdx.x * 128;
    int m0w = wm * 64, n0w = wn * 32;

    float acc[4][4][4];
#pragma unroll
    for (int a = 0; a < 4; a++)
#pragma unroll
        for (int b = 0; b < 4; b++)
#pragma unroll
            for (int c = 0; c < 4; c++) acc[a][b][c] = 0.f;

    for (int k0 = 0; k0 < CC; k0 += 16) {
        __syncthreads();
#pragma unroll
        for (int u = tid; u < 512; u += 256) {
            int row = u >> 2, q = u & 3;
            float4 v = *reinterpret_cast<const float4*>(X + (long)(m0 + row) * CC + k0 + q * 4);
            As[row][q * 4 + 0] = v.x; As[row][q * 4 + 1] = v.y;
            As[row][q * 4 + 2] = v.z; As[row][q * 4 + 3] = v.w;
            float4 w = *reinterpret_cast<const float4*>(Wm + (long)(n0 + row) * CC + k0 + q * 4);
            Bs[row][q * 4 + 0] = w.x; Bs[row][q * 4 + 1] = w.y;
            Bs[row][q * 4 + 2] = w.z; Bs[row][q * 4 + 3] = w.w;
        }
        __syncthreads();

#pragma unroll
        for (int ks = 0; ks < 16; ks += 8) {
            unsigned ahi[4][4], alo[4][4];
#pragma unroll
            for (int mt = 0; mt < 4; mt++) {
                int m = m0w + mt * 16 + g;
                int k = ks + tg;
                float a0 = As[m][k], a1 = As[m + 8][k], a2 = As[m][k + 4], a3 = As[m + 8][k + 4];
                ahi[mt][0] = f2tf(a0); alo[mt][0] = f2tf(a0 - __uint_as_float(ahi[mt][0]));
                ahi[mt][1] = f2tf(a1); alo[mt][1] = f2tf(a1 - __uint_as_float(ahi[mt][1]));
                ahi[mt][2] = f2tf(a2); alo[mt][2] = f2tf(a2 - __uint_as_float(ahi[mt][2]));
                ahi[mt][3] = f2tf(a3); alo[mt][3] = f2tf(a3 - __uint_as_float(ahi[mt][3]));
            }
            unsigned bhi[4][2], blo[4][2];
#pragma unroll
            for (int nt = 0; nt < 4; nt++) {
                int n = n0w + nt * 8 + g;
                float b0 = Bs[n][ks + tg], b1 = Bs[n][ks + tg + 4];
                bhi[nt][0] = f2tf(b0); blo[nt][0] = f2tf(b0 - __uint_as_float(bhi[nt][0]));
                bhi[nt][1] = f2tf(b1); blo[nt][1] = f2tf(b1 - __uint_as_float(bhi[nt][1]));
            }
#pragma unroll
            for (int mt = 0; mt < 4; mt++)
#pragma unroll
                for (int nt = 0; nt < 4; nt++) {
                    mma8(acc[mt][nt], ahi[mt], bhi[nt]);
                    mma8(acc[mt][nt], ahi[mt], blo[nt]);
                    mma8(acc[mt][nt], alo[mt], bhi[nt]);
                }
        }
    }

#pragma unroll
    for (int mt = 0; mt < 4; mt++)
#pragma unroll
        for (int nt = 0; nt < 4; nt++)
#pragma unroll
            for (int ci = 0; ci < 4; ci++) {
                long m = m0 + m0w + mt * 16 + g + 8 * (ci >> 1);
                int n = n0 + n0w + nt * 8 + 2 * tg + (ci & 1);
                out[m * CC + n] = acc[mt][nt][ci] + bb[n];
            }
}

// ---------------------------------------------------------------------------
// DFT stage via tf32 mma.
//   accR = A·xr + B·xi ;  accI = A·xi - B·xr   (A,B stage twiddles)
// CTA: one slice x 128-channel tile. 8 warps (2m x 4n), warp 32x32.
// ---------------------------------------------------------------------------
template <int STAGE>
__global__ __launch_bounds__(256) void dft_tc(const float* __restrict__ xin,
                                              float* __restrict__ xout) {
    constexpr bool INI  = (STAGE != 0);
    constexpr bool OUTI = (STAGE != 3);
    constexpr int  NKT  = (STAGE == 3) ? 5 : 8;   // k tiles of 8
    constexpr int  MOUT = (STAGE == 0) ? KWC : 64;

    __shared__ float sTA[64][68];
    __shared__ float sTB[64][68];
    __shared__ float Dr[8][136];
    __shared__ float Di[8][136];

    int tid = threadIdx.x;
    int wid = tid >> 5, lane = tid & 31;
    int g = lane >> 2, tg = lane & 3;
    int wm = wid >> 2, wn = wid & 3;
    int m0w = wm * 32, n0w = wn * 32;

    for (int i = tid; i < 4096; i += 256) {
        int k = i >> 6, m = i & 63;
        sTA[m][k] = g_twA[STAGE][i];
        sTB[m][k] = g_twB[STAGE][i];
    }

    int bi = blockIdx.x;
    int nb = blockIdx.y << 7;

    long ibase, obase;
    int iks, oms;
    if (STAGE == 0) {
        ibase = (long)bi * (WW * CC); iks = CC;
        obase = (long)bi * (KWC * CC); oms = CC;
    } else if (STAGE == 1 || STAGE == 2) {
        int b = bi / KWC, kw = bi % KWC;
        long base = (long)b * (HH * KWC * CC) + (long)kw * CC;
        ibase = base; obase = base;
        iks = KWC * CC; oms = KWC * CC;
    } else {
        ibase = (long)bi * (KWC * CC); iks = CC;
        obase = (long)bi * (WW * CC);  oms = CC;
    }

    const float* pir;
    const float* pii;
    float* por;
    float* poi;
    if (STAGE == 0)      { pir = xin + ibase;  pii = xin + ibase;  por = g_wr + obase; poi = g_wi + obase; }
    else if (STAGE == 1) { pir = g_wr + ibase; pii = g_wi + ibase; por = g_sr + obase; poi = g_si + obase; }
    else if (STAGE == 2) { pir = g_sr + ibase; pii = g_si + ibase; por = g_wr + obase; poi = g_wi + obase; }
    else                 { pir = g_wr + ibase; pii = g_wi + ibase; por = xout + obase; poi = xout + obase; }

    float accR[2][4][4], accI[2][4][4];
#pragma unroll
    for (int a = 0; a < 2; a++)
#pragma unroll
        for (int b = 0; b < 4; b++)
#pragma unroll
            for (int c = 0; c < 4; c++) { accR[a][b][c] = 0.f; accI[a][b][c] = 0.f; }

    __syncthreads();

    for (int kt = 0; kt < NKT; kt++) {
        int k0 = kt * 8;
        __syncthreads();
        {
            int kr = tid >> 5, q = tid & 31;
            float4 v = *reinterpret_cast<const float4*>(pir + (long)(k0 + kr) * iks + nb + q * 4);
            Dr[kr][q * 4 + 0] = v.x; Dr[kr][q * 4 + 1] = v.y;
            Dr[kr][q * 4 + 2] = v.z; Dr[kr][q * 4 + 3] = v.w;
            if (INI) {
                float4 w = *reinterpret_cast<const float4*>(pii + (long)(k0 + kr) * iks + nb + q * 4);
                Di[kr][q * 4 + 0] = w.x; Di[kr][q * 4 + 1] = w.y;
                Di[kr][q * 4 + 2] = w.z; Di[kr][q * 4 + 3] = w.w;
            }
        }
        __syncthreads();

        unsigned aA[2][4], aB[2][4], aBn[2][4];
#pragma unroll
        for (int mt = 0; mt < 2; mt++) {
            int m = m0w + mt * 16 + g;
            int k = k0 + tg;
            aA[mt][0] = f2tf(sTA[m][k]);     aA[mt][1] = f2tf(sTA[m + 8][k]);
            aA[mt][2] = f2tf(sTA[m][k + 4]); aA[mt][3] = f2tf(sTA[m + 8][k + 4]);
            aB[mt][0] = f2tf(sTB[m][k]);     aB[mt][1] = f2tf(sTB[m + 8][k]);
            aB[mt][2] = f2tf(sTB[m][k + 4]); aB[mt][3] = f2tf(sTB[m + 8][k + 4]);
#pragma unroll
            for (int j = 0; j < 4; j++) aBn[mt][j] = aB[mt][j] ^ 0x80000000u;
        }
        unsigned bR[4][2], bI[4][2];
#pragma unroll
        for (int nt = 0; nt < 4; nt++) {
            int n = n0w + nt * 8 + g;
            bR[nt][0] = f2tf(Dr[tg][n]);
            bR[nt][1] = f2tf(Dr[tg + 4][n]);
            if (INI) {
                bI[nt][0] = f2tf(Di[tg][n]);
                bI[nt][1] = f2tf(Di[tg + 4][n]);
            }
        }
#pragma unroll
        for (int mt = 0; mt < 2; mt++)
#pragma unroll
            for (int nt = 0; nt < 4; nt++) {
                mma8(accR[mt][nt], aA[mt], bR[nt]);
                if (INI) mma8(accR[mt][nt], aB[mt], bI[nt]);
                if (OUTI) {
                    if (INI) mma8(accI[mt][nt], aA[mt], bI[nt]);
                    mma8(accI[mt][nt], aBn[mt], bR[nt]);
                }
            }
    }

#pragma unroll
    for (int mt = 0; mt < 2; mt++)
#pragma unroll
        for (int nt = 0; nt < 4; nt++)
#pragma unroll
            for (int ci = 0; ci < 4; ci++) {
                int m = m0w + mt * 16 + g + 8 * (ci >> 1);
                int n = nb + n0w + nt * 8 + 2 * tg + (ci & 1);
                if (STAGE != 0 || m < MOUT) {
                    long o = (long)m * oms + n;
                    if (STAGE == 3) {
                        por[o] += accR[mt][nt][ci];
                    } else {
                        por[o] = accR[mt][nt][ci];
                        poi[o] = accI[mt][nt][ci];
                    }
                }
            }
}

// ---------------------------------------------------------------------------
// Spectral MLP passes (tf32 mma):
//   PASS1: R1 = relu(Xr·W1r - Xi·W1i + b1r); I1 = relu(Xr·W1i + Xi·W1r + b1i)
//   PASS2: R2 = R1·W2r - I1·W2i + b2r
//   PASS3: I2 = R2·W2i + I1·W2r + b2i
// M = 16896 positions, per-block K=N=192. CTA: 128 pos x 64 cols.
// ---------------------------------------------------------------------------
template <int PASS>
__global__ __launch_bounds__(256) void spec_pass(const float* __restrict__ w,
                                                 const float* __restrict__ bias) {
    constexpr bool DO_R = (PASS != 3);
    constexpr bool DO_I = (PASS != 2);
    constexpr bool RELU = (PASS == 1);

    __shared__ float Aa[128][20];
    __shared__ float Ab[128][20];
    __shared__ float Wp[16][72];
    __shared__ float Wq[16][72];

    int tid = threadIdx.x;
    int wid = tid >> 5, lane = tid & 31;
    int g = lane >> 2, tg = lane & 3;
    int wm = wid >> 1, wn = wid & 1;
    int m0w = wm * 32, n0w = wn * 32;

    int byi = blockIdx.y;
    int blk = byi / 3, nseg = byi % 3;
    int cb = blk * BS;
    int n0 = nseg * 64;
    long p0 = (long)blockIdx.x * 128;

    const float* Aact;
    const float* Bact;
    float* outR;
    float* outI;
    if (PASS == 1)      { Aact = g_sr; Bact = g_si; outR = g_wr; outI = g_wi; }
    else if (PASS == 2) { Aact = g_wr; Bact = g_wi; outR = g_sr; outI = g_sr; }
    else                { Aact = g_sr; Bact = g_wi; outR = g_si; outI = g_si; }
    const float* P = w + (long)blk * (BS * BS);
    const float* Q = w + (long)(NB + blk) * (BS * BS);

    float accR[2][4][4], accI[2][4][4];
#pragma unroll
    for (int a = 0; a < 2; a++)
#pragma unroll
        for (int b = 0; b < 4; b++)
#pragma unroll
            for (int c = 0; c < 4; c++) { accR[a][b][c] = 0.f; accI[a][b][c] = 0.f; }

    for (int kt = 0; kt < 12; kt++) {
        int k0 = kt * 16;
        __syncthreads();
#pragma unroll
        for (int u = tid; u < 512; u += 256) {
            int row = u >> 2, q = u & 3;
            float4 v = *reinterpret_cast<const float4*>(Aact + (p0 + row) * CC + cb + k0 + q * 4);
            Aa[row][q * 4 + 0] = v.x; Aa[row][q * 4 + 1] = v.y;
            Aa[row][q * 4 + 2] = v.z; Aa[row][q * 4 + 3] = v.w;
            float4 z = *reinterpret_cast<const float4*>(Bact + (p0 + row) * CC + cb + k0 + q * 4);
            Ab[row][q * 4 + 0] = z.x; Ab[row][q * 4 + 1] = z.y;
            Ab[row][q * 4 + 2] = z.z; Ab[row][q * 4 + 3] = z.w;
        }
        {
            int kr = tid >> 4, q = tid & 15;
            float4 v = *reinterpret_cast<const float4*>(P + (long)(k0 + kr) * BS + n0 + q * 4);
            Wp[kr][q * 4 + 0] = v.x; Wp[kr][q * 4 + 1] = v.y;
            Wp[kr][q * 4 + 2] = v.z; Wp[kr][q * 4 + 3] = v.w;
            float4 z = *reinterpret_cast<const float4*>(Q + (long)(k0 + kr) * BS + n0 + q * 4);
            Wq[kr][q * 4 + 0] = z.x; Wq[kr][q * 4 + 1] = z.y;
            Wq[kr][q * 4 + 2] = z.z; Wq[kr][q * 4 + 3] = z.w;
        }
        __syncthreads();

#pragma unroll
        for (int ks = 0; ks < 16; ks += 8) {
            unsigned aR[2][4], aI[2][4];
#pragma unroll
            for (int mt = 0; mt < 2; mt++) {
                int m = m0w + mt * 16 + g;
                int k = ks + tg;
                aR[mt][0] = f2tf(Aa[m][k]);     aR[mt][1] = f2tf(Aa[m + 8][k]);
                aR[mt][2] = f2tf(Aa[m][k + 4]); aR[mt][3] = f2tf(Aa[m + 8][k + 4]);
                aI[mt][0] = f2tf(Ab[m][k]);     aI[mt][1] = f2tf(Ab[m + 8][k]);
                aI[mt][2] = f2tf(Ab[m][k + 4]); aI[mt][3] = f2tf(Ab[m + 8][k + 4]);
            }
            unsigned bP[4][2], bQ[4][2], bQn[4][2];
#pragma unroll
            for (int nt = 0; nt < 4; nt++) {
                int n = n0w + nt * 8 + g;
                bP[nt][0] = f2tf(Wp[ks + tg][n]);
                bP[nt][1] = f2tf(Wp[ks + tg + 4][n]);
                bQ[nt][0] = f2tf(Wq[ks + tg][n]);
                bQ[nt][1] = f2tf(Wq[ks + tg + 4][n]);
                bQn[nt][0] = bQ[nt][0] ^ 0x80000000u;
                bQn[nt][1] = bQ[nt][1] ^ 0x80000000u;
            }
#pragma unroll
            for (int mt = 0; mt < 2; mt++)
#pragma unroll
                for (int nt = 0; nt < 4; nt++) {
                    if (DO_R) {
                        mma8(accR[mt][nt], aR[mt], bP[nt]);
                        mma8(accR[mt][nt], aI[mt], bQn[nt]);
                    }
                    if (DO_I) {
                        mma8(accI[mt][nt], aR[mt], bQ[nt]);
                        mma8(accI[mt][nt], aI[mt], bP[nt]);
                    }
                }
        }
    }

    const float* bRv = bias + blk * BS;
    const float* bIv = bias + (NB + blk) * BS;
#pragma unroll
    for (int mt = 0; mt < 2; mt++)
#pragma unroll
        for (int nt = 0; nt < 4; nt++)
#pragma unroll
            for (int ci = 0; ci < 4; ci++) {
                long m = p0 + m0w + mt * 16 + g + 8 * (ci >> 1);
                int nl = n0 + n0w + nt * 8 + 2 * tg + (ci & 1);
                int ng = cb + nl;
                if (DO_R) {
                    float v = accR[mt][nt][ci] + bRv[nl];
                    if (RELU) v = fmaxf(v, 0.f);
                    outR[m * CC + ng] = v;
                }
                if (DO_I) {
                    float v = accI[mt][nt][ci] + bIv[nl];
                    if (RELU) v = fmaxf(v, 0.f);
                    outI[m * CC + ng] = v;
                }
            }
}

// ---------------------------------------------------------------------------
extern "C" void kernel_launch(void* const* d_in, const int* in_sizes, int n_in,
                              void* d_out, int out_size) {
    const float* x   = (const float*)d_in[0];
    const float* w1  = (const float*)d_in[1];
    const float* b1  = (const float*)d_in[2];
    const float* w2  = (const float*)d_in[3];
    const float* b2  = (const float*)d_in[4];
    const float* bw  = (const float*)d_in[5];
    const float* bbv = (const float*)d_in[6];
    float* out = (float*)d_out;

    fill_tw_kernel<<<1, 256>>>();

    // bias = x @ bias_w^T + bias_b (3xTF32, writes every out element)
    bias_gemm_tc<<<dim3(6, 256), 256>>>(x, bw, bbv, out);

    // forward rFFT along W: x -> g_w
    dft_tc<0><<<dim3(BB * HH, 6), 256>>>(x, out);
    // forward FFT along H (ortho /64): g_w -> g_s
    dft_tc<1><<<dim3(BB * KWC, 6), 256>>>(x, out);
    // spectral block MLP
    spec_pass<1><<<dim3(132, 12), 256>>>(w1, b1);   // g_s -> g_w (R1, I1)
    spec_pass<2><<<dim3(132, 12), 256>>>(w2, b2);   // g_w -> g_sr (R2)
    spec_pass<3><<<dim3(132, 12), 256>>>(w2, b2);   // g_sr,g_wi -> g_si (I2)
    // inverse FFT along H: g_s -> g_w
    dft_tc<2><<<dim3(BB * KWC, 6), 256>>>(x, out);
    // inverse rFFT along W, accumulate into out
    dft_tc<3><<<dim3(BB * HH, 6), 256>>>(x, out);
}